// round 15
// baseline (speedup 1.0000x reference)
#include <cuda_runtime.h>
#include <cuda_fp16.h>
#include <cuda_fp8.h>

#define NUM_USERS 100000
#define N_NODES   150000
#define D         64
#define EDGES     2000000
#define BATCH     1024
#define SCAN_B    1024
#define NBLK      ((N_NODES + SCAN_B - 1) / SCAN_B)   // 147
#define CSRMAX    (EDGES + 8 * N_NODES)               // padded CSR capacity
#define FSCALE    128.0f                              // fp8 storage scale
#define NBUCKET   64

// ---------------- scratch (device globals: allocation-free) ----------------
struct Zeros {
    int   deg[N_NODES];              // row histogram
    int   colcnt[N_NODES];           // col histogram
    int   cnt8[N_NODES / 4];         // batch-user multiplicity, packed uint8
    int   nbkt[NBUCKET];             // node count per n8 bucket
    float usum[D];
    float acc[D];
    float z;
    int   flags[NBLK];
};
__device__ Zeros  g_zs;                          // ~1.4 MB, memset once per call
// fp8(e5m2) y-buffers: row = 64 bytes = 4 uint4. Row N_NODES is the zero
// sentinel: zero-initialized at load, never written (all writers use node<N).
__device__ uint4  g_f0[(size_t)(N_NODES + 1) * 4];
__device__ uint4  g_f1[(size_t)(N_NODES + 1) * 4];
__device__ __half g_xh[(size_t)N_NODES * D];     // 19.2 MB final layer (fp16)
__device__ int    g_csr_row[CSRMAX];             // src row, col-sorted, 8-padded
__device__ int    g_off[N_NODES + 1];
__device__ int    g_pos[N_NODES];
__device__ float  g_dinv[N_NODES];               // deg^-1/2 per node
__device__ int    g_aggval[NBLK];                // gated by flags; no zeroing
__device__ int    g_bpos[NBUCKET];               // bucket cursors (bscan rewrites)
__device__ int2   g_sinfo[N_NODES];              // degree-sorted {off, node|(n8<<18)}

__device__ __forceinline__ unsigned short h2_f8(__half2 h) {     // rounded store
    __half2_raw r = *reinterpret_cast<__half2_raw*>(&h);
    return (unsigned short)__nv_cvt_halfraw2_to_fp8x2(r, __NV_SATFINITE, __NV_E5M2);
}
__device__ __forceinline__ unsigned short f2_f8(float a, float b) {
    return (unsigned short)__nv_cvt_float2_to_fp8x2(make_float2(a, b),
                                                    __NV_SATFINITE, __NV_E5M2);
}
__device__ __forceinline__ __half2 u2h2(unsigned u) {
    __half2 h; *reinterpret_cast<unsigned*>(&h) = u; return h;
}
// e5m2 -> half is EXACT byte placement: half bits = fp8 byte << 8.
__device__ __forceinline__ __half2 e5m2_lo(unsigned v) { return u2h2(__byte_perm(v, 0, 0x1404)); }
__device__ __forceinline__ __half2 e5m2_hi(unsigned v) { return u2h2(__byte_perm(v, 0, 0x3424)); }

// ---------------- histograms only ------------------------------------------
__global__ void hist_k(const int* __restrict__ row, const int* __restrict__ col) {
    int t = blockIdx.x * blockDim.x + threadIdx.x;
    if (t < EDGES) {
        atomicAdd(&g_zs.deg[row[t]], 1);
        atomicAdd(&g_zs.colcnt[col[t]], 1);
    }
}

// ---------------- one-kernel scan over PADDED counts + dinv + pad-fill -----
// Also builds the n8-bucket histogram (block-aggregated).
__global__ void __launch_bounds__(1024) scan_k() {
    __shared__ int sh[SCAN_B];
    __shared__ int s_warp[32];
    __shared__ int s_pref;
    __shared__ int s_bkt[NBUCKET];
    int b   = blockIdx.x;
    int tid = threadIdx.x;
    int i   = b * SCAN_B + tid;
    if (tid < NBUCKET) s_bkt[tid] = 0;
    int cnt = (i < N_NODES) ? g_zs.colcnt[i] : 0;
    int v   = (cnt + 7) & ~7;                    // pad to 8
    int n8  = min(v >> 3, NBUCKET - 1);
    sh[tid] = v;
    __syncthreads();
    if (i < N_NODES) atomicAdd(&s_bkt[n8], 1);   // shared, low contention
    for (int d = 1; d < SCAN_B; d <<= 1) {
        int t = (tid >= d) ? sh[tid - d] : 0;
        __syncthreads();
        sh[tid] += t;
        __syncthreads();
    }
    int incl = sh[tid];
    if (tid == SCAN_B - 1) {                     // publish aggregate first
        atomicExch(&g_aggval[b], incl);
        __threadfence();
        atomicExch(&g_zs.flags[b], 1);
    }
    if (tid < NBUCKET && s_bkt[tid])             // one global atomic per bucket
        atomicAdd(&g_zs.nbkt[tid], s_bkt[tid]);
    if (i < N_NODES)                             // free rider: dinv
        g_dinv[i] = rsqrtf(fmaxf((float)g_zs.deg[i], 1.0f));
    int pv = 0;
    if (tid < b) {
        while (atomicAdd(&g_zs.flags[tid], 0) == 0) { }
        pv = atomicAdd(&g_aggval[tid], 0);
    }
    #pragma unroll
    for (int o = 16; o; o >>= 1) pv += __shfl_xor_sync(0xffffffffu, pv, o);
    if ((tid & 31) == 0) s_warp[tid >> 5] = pv;
    __syncthreads();
    if (tid < 32) {
        int w = s_warp[tid];
        #pragma unroll
        for (int o = 16; o; o >>= 1) w += __shfl_xor_sync(0xffffffffu, w, o);
        if (tid == 0) s_pref = w;
    }
    __syncthreads();
    if (i < N_NODES) {
        int off = incl - v + s_pref;
        g_off[i] = off;
        g_pos[i] = off;
        if (i == N_NODES - 1) g_off[N_NODES] = off + v;
        // fill ONLY the <=7 pad slots with the zero-sentinel row index
        for (int q = off + cnt; q < off + v; q++) g_csr_row[q] = N_NODES;
    }
}

// ---------------- tiny: exclusive scan over 64 bucket counts ---------------
__global__ void bscan_k() {
    __shared__ int sh[NBUCKET];
    int tid = threadIdx.x;
    sh[tid] = g_zs.nbkt[tid];
    __syncthreads();
    int acc = 0;
    for (int j = 0; j < NBUCKET; j++) { if (j == tid) break; acc += sh[j]; }
    g_bpos[tid] = acc;
}

// ---------------- fused: CSR scatter + y0 conv + degree-sort perm ----------
__global__ void scatconv_k(const int* __restrict__ row, const int* __restrict__ col,
                           const float4* __restrict__ embed, uint4* __restrict__ f0) {
    __shared__ int s_cnt[NBUCKET];
    __shared__ int s_base[NBUCKET];
    int t = blockIdx.x * blockDim.x + threadIdx.x;
    int tid = threadIdx.x;
    if (tid < NBUCKET) s_cnt[tid] = 0;
    __syncthreads();
    // job 3: degree-sorted permutation (rank within bucket via shared atomics)
    int n8 = 0, rank = 0, myoff = 0;
    bool donode = (t < N_NODES);
    if (donode) {
        int cnt = g_zs.colcnt[t];
        int v = (cnt + 7) & ~7;
        n8 = min(v >> 3, NBUCKET - 1);
        myoff = g_off[t];
        rank = atomicAdd(&s_cnt[n8], 1);
    }
    __syncthreads();
    if (tid < NBUCKET && s_cnt[tid])
        s_base[tid] = atomicAdd(&g_bpos[tid], s_cnt[tid]);
    __syncthreads();
    if (donode) {
        int p = s_base[n8] + rank;
        g_sinfo[p] = make_int2(myoff, t | (n8 << 18));
    }
    // job 1: counting-sort edge scatter
    if (t < EDGES) {
        int p = atomicAdd(&g_pos[col[t]], 1);
        g_csr_row[p] = row[t];
    }
    // job 2: y0 = dinv*embed*S -> fp8
    if (t < N_NODES * 4) {
        int node = t >> 2, lane = t & 3;
        float sc = g_dinv[node] * FSCALE;
        const float4* p = embed + (size_t)node * 16 + lane * 4;
        float4 v0 = p[0], v1 = p[1], v2 = p[2], v3 = p[3];
        uint4 o;
        o.x = (unsigned)f2_f8(v0.x * sc, v0.y * sc) | ((unsigned)f2_f8(v0.z * sc, v0.w * sc) << 16);
        o.y = (unsigned)f2_f8(v1.x * sc, v1.y * sc) | ((unsigned)f2_f8(v1.z * sc, v1.w * sc) << 16);
        o.z = (unsigned)f2_f8(v2.x * sc, v2.y * sc) | ((unsigned)f2_f8(v2.z * sc, v2.w * sc) << 16);
        o.w = (unsigned)f2_f8(v3.x * sc, v3.y * sc) | ((unsigned)f2_f8(v3.z * sc, v3.w * sc) << 16);
        f0[(size_t)node * 4 + lane] = o;
    }
}

// ---------------- one propagation layer: e5m2 gather, degree-sorted --------
__device__ __forceinline__ void acc16(__half2* a, uint4 v) {
    a[0] = __hadd2(a[0], e5m2_lo(v.x));
    a[1] = __hadd2(a[1], e5m2_hi(v.x));
    a[2] = __hadd2(a[2], e5m2_lo(v.y));
    a[3] = __hadd2(a[3], e5m2_hi(v.y));
    a[4] = __hadd2(a[4], e5m2_lo(v.z));
    a[5] = __hadd2(a[5], e5m2_hi(v.z));
    a[6] = __hadd2(a[6], e5m2_lo(v.w));
    a[7] = __hadd2(a[7], e5m2_hi(v.w));
}

template <bool F8_OUT>
__global__ void __launch_bounds__(256) prop_f8_k(const uint4* __restrict__ yin,
                                                 void* __restrict__ out_v) {
    unsigned t = blockIdx.x * blockDim.x + threadIdx.x;
    unsigned p = t >> 2;                   // degree-sorted position
    unsigned lane = t & 3;
    if (p >= N_NODES) return;
    int2 info = g_sinfo[p];                // streaming load
    int s = info.x;
    unsigned node = (unsigned)info.y & 0x3FFFFu;
    int n8 = (unsigned)info.y >> 18;       // identical across the warp's nodes
    const int4* cp = (const int4*)(g_csr_row + s);   // 32B-aligned (s % 8 == 0)
    __half2 a[8];
    #pragma unroll
    for (int j = 0; j < 8; j++) a[j] = __float2half2_rn(0.f);
    for (int j = 0; j < n8; j++) {
        int4 ca = cp[2 * j];
        int4 cb = cp[2 * j + 1];
        uint4 v0 = yin[(size_t)ca.x * 4 + lane];
        uint4 v1 = yin[(size_t)ca.y * 4 + lane];
        uint4 v2 = yin[(size_t)ca.z * 4 + lane];
        uint4 v3 = yin[(size_t)ca.w * 4 + lane];
        uint4 v4 = yin[(size_t)cb.x * 4 + lane];
        uint4 v5 = yin[(size_t)cb.y * 4 + lane];
        uint4 v6 = yin[(size_t)cb.z * 4 + lane];
        uint4 v7 = yin[(size_t)cb.w * 4 + lane];
        acc16(a, v0); acc16(a, v1); acc16(a, v2); acc16(a, v3);
        acc16(a, v4); acc16(a, v5); acc16(a, v6); acc16(a, v7);
    }
    float di = g_dinv[node];
    if (F8_OUT) {
        // y_next(scaled) = dinv^2 * sum(scaled)  -- S carries through unchanged
        __half2 sc = __float2half2_rn(di * di);
        uint4 o;
        o.x = (unsigned)h2_f8(__hmul2(a[0], sc)) | ((unsigned)h2_f8(__hmul2(a[1], sc)) << 16);
        o.y = (unsigned)h2_f8(__hmul2(a[2], sc)) | ((unsigned)h2_f8(__hmul2(a[3], sc)) << 16);
        o.z = (unsigned)h2_f8(__hmul2(a[4], sc)) | ((unsigned)h2_f8(__hmul2(a[5], sc)) << 16);
        o.w = (unsigned)h2_f8(__hmul2(a[6], sc)) | ((unsigned)h2_f8(__hmul2(a[7], sc)) << 16);
        ((uint4*)out_v)[(size_t)node * 4 + lane] = o;
    } else {
        // x3 = dinv * sum(scaled) / S   (fp16 for the epilogue; f32 math)
        float sc = di * (1.0f / FSCALE);
        __half2 oh[8];
        #pragma unroll
        for (int j = 0; j < 8; j++) {
            float2 f = __half22float2(a[j]);
            oh[j] = __floats2half2_rn(f.x * sc, f.y * sc);
        }
        uint4* q = (uint4*)out_v + (size_t)node * 8 + lane * 2;  // 16 halves
        uint4 o0, o1;
        o0.x = *reinterpret_cast<unsigned*>(&oh[0]);
        o0.y = *reinterpret_cast<unsigned*>(&oh[1]);
        o0.z = *reinterpret_cast<unsigned*>(&oh[2]);
        o0.w = *reinterpret_cast<unsigned*>(&oh[3]);
        o1.x = *reinterpret_cast<unsigned*>(&oh[4]);
        o1.y = *reinterpret_cast<unsigned*>(&oh[5]);
        o1.z = *reinterpret_cast<unsigned*>(&oh[6]);
        o1.w = *reinterpret_cast<unsigned*>(&oh[7]);
        q[0] = o0; q[1] = o1;
    }
}

// ---------------- fused: batch user counts (uint8) + context sum -----------
__global__ void epi1_k(const int* __restrict__ users, const __half* __restrict__ xh) {
    int b = blockIdx.x, tid = threadIdx.x;
    if (tid < 64) {
        float s = 0.0f;
        #pragma unroll 8
        for (int k = 0; k < 64; k++) {
            int u = users[b * 64 + k];
            s += __half2float(xh[(size_t)u * D + tid]);
        }
        atomicAdd(&g_zs.usum[tid], s);
    } else {
        int u = users[b * 64 + (tid - 64)];
        atomicAdd(&g_zs.cnt8[u >> 2], 1 << ((u & 3) * 8));   // packed uint8
    }
}

// ---------------- softmax-weighted neighbor aggregation over edges ---------
// mx subtraction skipped: cancels exactly in acc/z; clip(1e-12) cannot bind.
__global__ void __launch_bounds__(256) softmax_k(const int* __restrict__ row,
                                                 const int* __restrict__ col,
                                                 const __half* __restrict__ xh) {
    __shared__ float s_us[D];
    __shared__ float s_acc[D];
    __shared__ float s_z;
    int tid = threadIdx.x;
    if (tid < D) {
        s_us[tid]  = g_zs.usum[tid] * (1.0f / (float)BATCH);
        s_acc[tid] = 0.0f;
    }
    if (tid == 0) s_z = 0.0f;
    __syncthreads();

    const unsigned char* cnt8 = (const unsigned char*)g_zs.cnt8;  // 150KB
    int stride = gridDim.x * blockDim.x;
    for (int e = blockIdx.x * blockDim.x + tid; e < EDGES; e += stride) {
        unsigned m = cnt8[row[e]];
        if (m) {                             // ~0.7% of edges
            const uint4* nv = (const uint4*)(xh + (size_t)col[e] * D);  // 8x16B
            float2 vv[32];
            float dot = 0.0f;
            #pragma unroll
            for (int i = 0; i < 8; i++) {
                uint4 q = nv[i];
                vv[4*i+0] = __half22float2(u2h2(q.x));
                vv[4*i+1] = __half22float2(u2h2(q.y));
                vv[4*i+2] = __half22float2(u2h2(q.z));
                vv[4*i+3] = __half22float2(u2h2(q.w));
            }
            #pragma unroll
            for (int i = 0; i < 32; i++)
                dot += vv[i].x * s_us[2*i] + vv[i].y * s_us[2*i+1];
            float w = (float)m * __expf(dot);
            atomicAdd(&s_z, w);
            #pragma unroll
            for (int i = 0; i < 32; i++) {
                atomicAdd(&s_acc[2*i],   w * vv[i].x);
                atomicAdd(&s_acc[2*i+1], w * vv[i].y);
            }
        }
    }
    __syncthreads();
    if (tid < D) atomicAdd(&g_zs.acc[tid], s_acc[tid]);
    if (tid == 0) atomicAdd(&g_zs.z, s_z);
}

// ---------------- final scores: sigmoid(u.i + u.(acc/z)) -------------------
__global__ void score_k(const int* __restrict__ users, const int* __restrict__ items,
                        const __half* __restrict__ xh, float* __restrict__ out) {
    int w = (blockIdx.x * blockDim.x + threadIdx.x) >> 5;
    int lane = threadIdx.x & 31;
    if (w >= BATCH) return;
    int u  = users[w];
    int it = items[w] + NUM_USERS;
    float zc = fmaxf(g_zs.z, 1e-12f);
    float2 ue = __half22float2(((const __half2*)(xh + (size_t)u  * D))[lane]);
    float2 ie = __half22float2(((const __half2*)(xh + (size_t)it * D))[lane]);
    float2 ac = ((const float2*)g_zs.acc)[lane];
    float s = ue.x * ie.x + ue.y * ie.y + (ue.x * ac.x + ue.y * ac.y) / zc;
    #pragma unroll
    for (int o = 16; o; o >>= 1) s += __shfl_xor_sync(0xffffffffu, s, o);
    if (lane == 0) out[w] = 1.0f / (1.0f + __expf(-s));
}

// ---------------- launcher (graph-capturable, allocation-free) -------------
extern "C" void kernel_launch(void* const* d_in, const int* in_sizes, int n_in,
                              void* d_out, int out_size) {
    const float* embed = (const float*)d_in[0];        // [150000, 64] f32
    const int*   row   = (const int*)d_in[1];          // edge_index[0]
    const int*   col   = row + EDGES;                  // edge_index[1]
    const int*   users = (const int*)d_in[2];          // [1024] i32
    const int*   items = (const int*)d_in[3];          // [1024] i32
    float*       out   = (float*)d_out;                // [1024] f32

    void *zsp, *f0p, *f1p, *xhp;
    cudaGetSymbolAddress(&zsp, g_zs);
    cudaGetSymbolAddress(&f0p, g_f0);
    cudaGetSymbolAddress(&f1p, g_f1);
    cudaGetSymbolAddress(&xhp, g_xh);
    const __half* xh = (const __half*)xhp;

    const int EB  = (EDGES + 255) / 256;                // edge-parallel blocks
    const int PB4 = (N_NODES * 4 + 255) / 256;          // 4 threads/node blocks

    cudaMemsetAsync(zsp, 0, sizeof(Zeros));

    hist_k<<<EB, 256>>>(row, col);                      // histograms
    scan_k<<<NBLK, SCAN_B>>>();                         // off/pos + dinv + buckets
    bscan_k<<<1, NBUCKET>>>();                          // bucket offsets
    scatconv_k<<<EB, 256>>>(row, col, (const float4*)embed, (uint4*)f0p);

    // 3 propagation layers, degree-sorted: f0 -> f1 -> f0 -> xh (fp16)
    prop_f8_k<true ><<<PB4, 256>>>((const uint4*)f0p, f1p);
    prop_f8_k<true ><<<PB4, 256>>>((const uint4*)f1p, f0p);
    prop_f8_k<false><<<PB4, 256>>>((const uint4*)f0p, xhp);

    // batch epilogue (fp16 final layer)
    epi1_k<<<16, 128>>>(users, xh);
    softmax_k<<<1184, 256>>>(row, col, xh);
    score_k<<<BATCH * 32 / 256, 256>>>(users, items, xh, out);
}

// round 16
// speedup vs baseline: 1.0290x; 1.0290x over previous
#include <cuda_runtime.h>
#include <cuda_fp16.h>
#include <cuda_fp8.h>

#define NUM_USERS 100000
#define N_NODES   150000
#define D         64
#define EDGES     2000000
#define BATCH     1024
#define SCAN_B    1024
#define NBLK      ((N_NODES + SCAN_B - 1) / SCAN_B)   // 147
#define CSRMAX    (EDGES + 8 * N_NODES)               // padded CSR capacity
#define FSCALE    128.0f                              // fp8 storage scale
#define NBUCKET   64

// ---------------- scratch (device globals: allocation-free) ----------------
struct Zeros {
    int   deg[N_NODES];              // row histogram
    int   colcnt[N_NODES];           // col histogram
    int   cnt8[N_NODES / 4];         // batch-user multiplicity, packed uint8
    int   nbkt[NBUCKET];             // node count per n8 bucket
    float usum[D];
    float acc[D];
    float z;
    int   flags[NBLK];
};
__device__ Zeros  g_zs;                          // ~1.4 MB, memset once per call
// fp8(e5m2) y-buffers: row = 64 bytes = 4 uint4. Row N_NODES is the zero
// sentinel: zero-initialized at load, never written (all writers use node<N).
__device__ uint4  g_f0[(size_t)(N_NODES + 1) * 4];
__device__ uint4  g_f1[(size_t)(N_NODES + 1) * 4];
__device__ __half g_xh[(size_t)N_NODES * D];     // 19.2 MB final layer (fp16)
__device__ int    g_csr_row[CSRMAX];             // src row, col-sorted, 8-padded
__device__ int    g_off[N_NODES + 1];
__device__ int    g_pos[N_NODES];
__device__ float  g_dinv[N_NODES];               // deg^-1/2 per node
__device__ int    g_aggval[NBLK];                // gated by flags; no zeroing
__device__ int    g_bpos[NBUCKET];               // bucket cursors (bscan rewrites)
__device__ int2   g_sinfo[N_NODES];              // degree-sorted {off, node|(n8<<18)}

__device__ __forceinline__ unsigned short h2_f8(__half2 h) {     // rounded store
    __half2_raw r = *reinterpret_cast<__half2_raw*>(&h);
    return (unsigned short)__nv_cvt_halfraw2_to_fp8x2(r, __NV_SATFINITE, __NV_E5M2);
}
__device__ __forceinline__ unsigned short f2_f8(float a, float b) {
    return (unsigned short)__nv_cvt_float2_to_fp8x2(make_float2(a, b),
                                                    __NV_SATFINITE, __NV_E5M2);
}
__device__ __forceinline__ __half2 u2h2(unsigned u) {
    __half2 h; *reinterpret_cast<unsigned*>(&h) = u; return h;
}
// e5m2 -> half is EXACT byte placement: half bits = fp8 byte << 8.
__device__ __forceinline__ __half2 e5m2_lo(unsigned v) { return u2h2(__byte_perm(v, 0, 0x1404)); }
__device__ __forceinline__ __half2 e5m2_hi(unsigned v) { return u2h2(__byte_perm(v, 0, 0x3424)); }

// ---------------- histograms only ------------------------------------------
__global__ void hist_k(const int* __restrict__ row, const int* __restrict__ col) {
    int t = blockIdx.x * blockDim.x + threadIdx.x;
    if (t < EDGES) {
        atomicAdd(&g_zs.deg[row[t]], 1);
        atomicAdd(&g_zs.colcnt[col[t]], 1);
    }
}

// ---------------- one-kernel scan over PADDED counts + dinv + pad-fill -----
// Also builds the n8-bucket histogram (block-aggregated).
__global__ void __launch_bounds__(1024) scan_k() {
    __shared__ int sh[SCAN_B];
    __shared__ int s_warp[32];
    __shared__ int s_pref;
    __shared__ int s_bkt[NBUCKET];
    int b   = blockIdx.x;
    int tid = threadIdx.x;
    int i   = b * SCAN_B + tid;
    if (tid < NBUCKET) s_bkt[tid] = 0;
    int cnt = (i < N_NODES) ? g_zs.colcnt[i] : 0;
    int v   = (cnt + 7) & ~7;                    // pad to 8
    int n8  = min(v >> 3, NBUCKET - 1);
    sh[tid] = v;
    __syncthreads();
    if (i < N_NODES) atomicAdd(&s_bkt[n8], 1);   // shared, low contention
    for (int d = 1; d < SCAN_B; d <<= 1) {
        int t = (tid >= d) ? sh[tid - d] : 0;
        __syncthreads();
        sh[tid] += t;
        __syncthreads();
    }
    int incl = sh[tid];
    if (tid == SCAN_B - 1) {                     // publish aggregate first
        atomicExch(&g_aggval[b], incl);
        __threadfence();
        atomicExch(&g_zs.flags[b], 1);
    }
    if (tid < NBUCKET && s_bkt[tid])             // one global atomic per bucket
        atomicAdd(&g_zs.nbkt[tid], s_bkt[tid]);
    if (i < N_NODES)                             // free rider: dinv
        g_dinv[i] = rsqrtf(fmaxf((float)g_zs.deg[i], 1.0f));
    int pv = 0;
    if (tid < b) {
        while (atomicAdd(&g_zs.flags[tid], 0) == 0) { }
        pv = atomicAdd(&g_aggval[tid], 0);
    }
    #pragma unroll
    for (int o = 16; o; o >>= 1) pv += __shfl_xor_sync(0xffffffffu, pv, o);
    if ((tid & 31) == 0) s_warp[tid >> 5] = pv;
    __syncthreads();
    if (tid < 32) {
        int w = s_warp[tid];
        #pragma unroll
        for (int o = 16; o; o >>= 1) w += __shfl_xor_sync(0xffffffffu, w, o);
        if (tid == 0) s_pref = w;
    }
    __syncthreads();
    if (i < N_NODES) {
        int off = incl - v + s_pref;
        g_off[i] = off;
        g_pos[i] = off;
        if (i == N_NODES - 1) g_off[N_NODES] = off + v;
        // fill ONLY the <=7 pad slots with the zero-sentinel row index
        for (int q = off + cnt; q < off + v; q++) g_csr_row[q] = N_NODES;
    }
}

// ---------------- tiny: exclusive scan over 64 bucket counts ---------------
__global__ void bscan_k() {
    __shared__ int sh[NBUCKET];
    int tid = threadIdx.x;
    sh[tid] = g_zs.nbkt[tid];
    __syncthreads();
    int acc = 0;
    for (int j = 0; j < NBUCKET; j++) { if (j == tid) break; acc += sh[j]; }
    g_bpos[tid] = acc;
}

// ---------------- degree-sort permutation (standalone: uniform work, cheap
// barriers; kept OUT of the atomic-scatter kernel) ---------------------------
__global__ void perm_k() {
    __shared__ int s_cnt[NBUCKET];
    __shared__ int s_base[NBUCKET];
    int t = blockIdx.x * blockDim.x + threadIdx.x;
    int tid = threadIdx.x;
    if (tid < NBUCKET) s_cnt[tid] = 0;
    __syncthreads();
    int n8 = 0, rank = 0, myoff = 0;
    bool donode = (t < N_NODES);
    if (donode) {
        int cnt = g_zs.colcnt[t];
        int v = (cnt + 7) & ~7;
        n8 = min(v >> 3, NBUCKET - 1);
        myoff = g_off[t];
        rank = atomicAdd(&s_cnt[n8], 1);
    }
    __syncthreads();
    if (tid < NBUCKET && s_cnt[tid])
        s_base[tid] = atomicAdd(&g_bpos[tid], s_cnt[tid]);
    __syncthreads();
    if (donode)
        g_sinfo[s_base[n8] + rank] = make_int2(myoff, t | (n8 << 18));
}

// ---------------- fused: counting-sort scatter + y0 conv (NO barriers) -----
__global__ void scatconv_k(const int* __restrict__ row, const int* __restrict__ col,
                           const float4* __restrict__ embed, uint4* __restrict__ f0) {
    int t = blockIdx.x * blockDim.x + threadIdx.x;
    if (t < EDGES) {
        int p = atomicAdd(&g_pos[col[t]], 1);
        g_csr_row[p] = row[t];
    }
    if (t < N_NODES * 4) {
        int node = t >> 2, lane = t & 3;
        float sc = g_dinv[node] * FSCALE;
        const float4* p = embed + (size_t)node * 16 + lane * 4;
        float4 v0 = p[0], v1 = p[1], v2 = p[2], v3 = p[3];
        uint4 o;
        o.x = (unsigned)f2_f8(v0.x * sc, v0.y * sc) | ((unsigned)f2_f8(v0.z * sc, v0.w * sc) << 16);
        o.y = (unsigned)f2_f8(v1.x * sc, v1.y * sc) | ((unsigned)f2_f8(v1.z * sc, v1.w * sc) << 16);
        o.z = (unsigned)f2_f8(v2.x * sc, v2.y * sc) | ((unsigned)f2_f8(v2.z * sc, v2.w * sc) << 16);
        o.w = (unsigned)f2_f8(v3.x * sc, v3.y * sc) | ((unsigned)f2_f8(v3.z * sc, v3.w * sc) << 16);
        f0[(size_t)node * 4 + lane] = o;
    }
}

// ---------------- one propagation layer: e5m2 gather, degree-sorted --------
__device__ __forceinline__ void acc16(__half2* a, uint4 v) {
    a[0] = __hadd2(a[0], e5m2_lo(v.x));
    a[1] = __hadd2(a[1], e5m2_hi(v.x));
    a[2] = __hadd2(a[2], e5m2_lo(v.y));
    a[3] = __hadd2(a[3], e5m2_hi(v.y));
    a[4] = __hadd2(a[4], e5m2_lo(v.z));
    a[5] = __hadd2(a[5], e5m2_hi(v.z));
    a[6] = __hadd2(a[6], e5m2_lo(v.w));
    a[7] = __hadd2(a[7], e5m2_hi(v.w));
}

template <bool F8_OUT>
__global__ void __launch_bounds__(256) prop_f8_k(const uint4* __restrict__ yin,
                                                 void* __restrict__ out_v) {
    unsigned t = blockIdx.x * blockDim.x + threadIdx.x;
    unsigned p = t >> 2;                   // degree-sorted position
    unsigned lane = t & 3;
    if (p >= N_NODES) return;
    int2 info = g_sinfo[p];                // streaming load
    int s = info.x;
    unsigned node = (unsigned)info.y & 0x3FFFFu;
    int n8 = (unsigned)info.y >> 18;       // identical across the warp's nodes
    const int4* cp = (const int4*)(g_csr_row + s);   // 32B-aligned (s % 8 == 0)
    __half2 a[8];
    #pragma unroll
    for (int j = 0; j < 8; j++) a[j] = __float2half2_rn(0.f);
    for (int j = 0; j < n8; j++) {
        int4 ca = cp[2 * j];
        int4 cb = cp[2 * j + 1];
        uint4 v0 = yin[(size_t)ca.x * 4 + lane];
        uint4 v1 = yin[(size_t)ca.y * 4 + lane];
        uint4 v2 = yin[(size_t)ca.z * 4 + lane];
        uint4 v3 = yin[(size_t)ca.w * 4 + lane];
        uint4 v4 = yin[(size_t)cb.x * 4 + lane];
        uint4 v5 = yin[(size_t)cb.y * 4 + lane];
        uint4 v6 = yin[(size_t)cb.z * 4 + lane];
        uint4 v7 = yin[(size_t)cb.w * 4 + lane];
        acc16(a, v0); acc16(a, v1); acc16(a, v2); acc16(a, v3);
        acc16(a, v4); acc16(a, v5); acc16(a, v6); acc16(a, v7);
    }
    float di = g_dinv[node];
    if (F8_OUT) {
        // y_next(scaled) = dinv^2 * sum(scaled)  -- S carries through unchanged
        __half2 sc = __float2half2_rn(di * di);
        uint4 o;
        o.x = (unsigned)h2_f8(__hmul2(a[0], sc)) | ((unsigned)h2_f8(__hmul2(a[1], sc)) << 16);
        o.y = (unsigned)h2_f8(__hmul2(a[2], sc)) | ((unsigned)h2_f8(__hmul2(a[3], sc)) << 16);
        o.z = (unsigned)h2_f8(__hmul2(a[4], sc)) | ((unsigned)h2_f8(__hmul2(a[5], sc)) << 16);
        o.w = (unsigned)h2_f8(__hmul2(a[6], sc)) | ((unsigned)h2_f8(__hmul2(a[7], sc)) << 16);
        ((uint4*)out_v)[(size_t)node * 4 + lane] = o;
    } else {
        // x3 = dinv * sum(scaled) / S   (fp16 for the epilogue; f32 math)
        float sc = di * (1.0f / FSCALE);
        __half2 oh[8];
        #pragma unroll
        for (int j = 0; j < 8; j++) {
            float2 f = __half22float2(a[j]);
            oh[j] = __floats2half2_rn(f.x * sc, f.y * sc);
        }
        uint4* q = (uint4*)out_v + (size_t)node * 8 + lane * 2;  // 16 halves
        uint4 o0, o1;
        o0.x = *reinterpret_cast<unsigned*>(&oh[0]);
        o0.y = *reinterpret_cast<unsigned*>(&oh[1]);
        o0.z = *reinterpret_cast<unsigned*>(&oh[2]);
        o0.w = *reinterpret_cast<unsigned*>(&oh[3]);
        o1.x = *reinterpret_cast<unsigned*>(&oh[4]);
        o1.y = *reinterpret_cast<unsigned*>(&oh[5]);
        o1.z = *reinterpret_cast<unsigned*>(&oh[6]);
        o1.w = *reinterpret_cast<unsigned*>(&oh[7]);
        q[0] = o0; q[1] = o1;
    }
}

// ---------------- fused: batch user counts (uint8) + context sum -----------
__global__ void epi1_k(const int* __restrict__ users, const __half* __restrict__ xh) {
    int b = blockIdx.x, tid = threadIdx.x;
    if (tid < 64) {
        float s = 0.0f;
        #pragma unroll 8
        for (int k = 0; k < 64; k++) {
            int u = users[b * 64 + k];
            s += __half2float(xh[(size_t)u * D + tid]);
        }
        atomicAdd(&g_zs.usum[tid], s);
    } else {
        int u = users[b * 64 + (tid - 64)];
        atomicAdd(&g_zs.cnt8[u >> 2], 1 << ((u & 3) * 8));   // packed uint8
    }
}

// ---------------- softmax-weighted neighbor aggregation over edges ---------
// mx subtraction skipped: cancels exactly in acc/z; clip(1e-12) cannot bind.
__global__ void __launch_bounds__(256) softmax_k(const int* __restrict__ row,
                                                 const int* __restrict__ col,
                                                 const __half* __restrict__ xh) {
    __shared__ float s_us[D];
    __shared__ float s_acc[D];
    __shared__ float s_z;
    int tid = threadIdx.x;
    if (tid < D) {
        s_us[tid]  = g_zs.usum[tid] * (1.0f / (float)BATCH);
        s_acc[tid] = 0.0f;
    }
    if (tid == 0) s_z = 0.0f;
    __syncthreads();

    const unsigned char* cnt8 = (const unsigned char*)g_zs.cnt8;  // 150KB
    int stride = gridDim.x * blockDim.x;
    for (int e = blockIdx.x * blockDim.x + tid; e < EDGES; e += stride) {
        unsigned m = cnt8[row[e]];
        if (m) {                             // ~0.7% of edges
            const uint4* nv = (const uint4*)(xh + (size_t)col[e] * D);  // 8x16B
            float2 vv[32];
            float dot = 0.0f;
            #pragma unroll
            for (int i = 0; i < 8; i++) {
                uint4 q = nv[i];
                vv[4*i+0] = __half22float2(u2h2(q.x));
                vv[4*i+1] = __half22float2(u2h2(q.y));
                vv[4*i+2] = __half22float2(u2h2(q.z));
                vv[4*i+3] = __half22float2(u2h2(q.w));
            }
            #pragma unroll
            for (int i = 0; i < 32; i++)
                dot += vv[i].x * s_us[2*i] + vv[i].y * s_us[2*i+1];
            float w = (float)m * __expf(dot);
            atomicAdd(&s_z, w);
            #pragma unroll
            for (int i = 0; i < 32; i++) {
                atomicAdd(&s_acc[2*i],   w * vv[i].x);
                atomicAdd(&s_acc[2*i+1], w * vv[i].y);
            }
        }
    }
    __syncthreads();
    if (tid < D) atomicAdd(&g_zs.acc[tid], s_acc[tid]);
    if (tid == 0) atomicAdd(&g_zs.z, s_z);
}

// ---------------- final scores: sigmoid(u.i + u.(acc/z)) -------------------
__global__ void score_k(const int* __restrict__ users, const int* __restrict__ items,
                        const __half* __restrict__ xh, float* __restrict__ out) {
    int w = (blockIdx.x * blockDim.x + threadIdx.x) >> 5;
    int lane = threadIdx.x & 31;
    if (w >= BATCH) return;
    int u  = users[w];
    int it = items[w] + NUM_USERS;
    float zc = fmaxf(g_zs.z, 1e-12f);
    float2 ue = __half22float2(((const __half2*)(xh + (size_t)u  * D))[lane]);
    float2 ie = __half22float2(((const __half2*)(xh + (size_t)it * D))[lane]);
    float2 ac = ((const float2*)g_zs.acc)[lane];
    float s = ue.x * ie.x + ue.y * ie.y + (ue.x * ac.x + ue.y * ac.y) / zc;
    #pragma unroll
    for (int o = 16; o; o >>= 1) s += __shfl_xor_sync(0xffffffffu, s, o);
    if (lane == 0) out[w] = 1.0f / (1.0f + __expf(-s));
}

// ---------------- launcher (graph-capturable, allocation-free) -------------
extern "C" void kernel_launch(void* const* d_in, const int* in_sizes, int n_in,
                              void* d_out, int out_size) {
    const float* embed = (const float*)d_in[0];        // [150000, 64] f32
    const int*   row   = (const int*)d_in[1];          // edge_index[0]
    const int*   col   = row + EDGES;                  // edge_index[1]
    const int*   users = (const int*)d_in[2];          // [1024] i32
    const int*   items = (const int*)d_in[3];          // [1024] i32
    float*       out   = (float*)d_out;                // [1024] f32

    void *zsp, *f0p, *f1p, *xhp;
    cudaGetSymbolAddress(&zsp, g_zs);
    cudaGetSymbolAddress(&f0p, g_f0);
    cudaGetSymbolAddress(&f1p, g_f1);
    cudaGetSymbolAddress(&xhp, g_xh);
    const __half* xh = (const __half*)xhp;

    const int EB  = (EDGES + 255) / 256;                // edge-parallel blocks
    const int NB  = (N_NODES + 255) / 256;              // node-parallel blocks
    const int PB4 = (N_NODES * 4 + 255) / 256;          // 4 threads/node blocks

    cudaMemsetAsync(zsp, 0, sizeof(Zeros));

    hist_k<<<EB, 256>>>(row, col);                      // histograms
    scan_k<<<NBLK, SCAN_B>>>();                         // off/pos + dinv + buckets
    bscan_k<<<1, NBUCKET>>>();                          // bucket offsets
    perm_k<<<NB, 256>>>();                              // degree-sort permutation
    scatconv_k<<<EB, 256>>>(row, col, (const float4*)embed, (uint4*)f0p);

    // 3 propagation layers, degree-sorted: f0 -> f1 -> f0 -> xh (fp16)
    prop_f8_k<true ><<<PB4, 256>>>((const uint4*)f0p, f1p);
    prop_f8_k<true ><<<PB4, 256>>>((const uint4*)f1p, f0p);
    prop_f8_k<false><<<PB4, 256>>>((const uint4*)f0p, xhp);

    // batch epilogue (fp16 final layer)
    epi1_k<<<16, 128>>>(users, xh);
    softmax_k<<<1184, 256>>>(row, col, xh);
    score_k<<<BATCH * 32 / 256, 256>>>(users, items, xh, out);
}

// round 17
// speedup vs baseline: 1.0411x; 1.0118x over previous
#include <cuda_runtime.h>
#include <cuda_fp16.h>
#include <cuda_fp8.h>

#define NUM_USERS 100000
#define N_NODES   150000
#define D         64
#define EDGES     2000000
#define BATCH     1024
#define SCAN_B    1024
#define NBLK      ((N_NODES + SCAN_B - 1) / SCAN_B)   // 147
#define CSRMAX    (EDGES + 4 * N_NODES)               // padded CSR capacity (pad-4)
#define FSCALE    128.0f                              // fp8 storage scale

// ---------------- scratch (device globals: allocation-free) ----------------
struct Zeros {
    int   deg[N_NODES];              // row histogram
    int   colcnt[N_NODES];           // col histogram
    int   cnt8[N_NODES / 4];         // batch-user multiplicity, packed uint8
    float usum[D];
    float acc[D];
    float z;
    int   flags[NBLK];
};
__device__ Zeros  g_zs;                          // ~1.4 MB, memset once per call
// fp8(e5m2) y-buffers: row = 64 bytes = 4 uint4. Row N_NODES is the zero
// sentinel: zero-initialized at load, never written (all writers use node<N).
__device__ uint4  g_f0[(size_t)(N_NODES + 1) * 4];
__device__ uint4  g_f1[(size_t)(N_NODES + 1) * 4];
__device__ __half g_xh[(size_t)N_NODES * D];     // 19.2 MB final layer (fp16)
__device__ int    g_csr_row[CSRMAX];             // src row, col-sorted, 4-padded
__device__ int    g_off[N_NODES + 1];
__device__ int    g_pos[N_NODES];
__device__ float  g_dinv[N_NODES];               // deg^-1/2 per node
__device__ int    g_aggval[NBLK];                // gated by flags; no zeroing

__device__ __forceinline__ unsigned short h2_f8(__half2 h) {     // rounded store
    __half2_raw r = *reinterpret_cast<__half2_raw*>(&h);
    return (unsigned short)__nv_cvt_halfraw2_to_fp8x2(r, __NV_SATFINITE, __NV_E5M2);
}
__device__ __forceinline__ unsigned short f2_f8(float a, float b) {
    return (unsigned short)__nv_cvt_float2_to_fp8x2(make_float2(a, b),
                                                    __NV_SATFINITE, __NV_E5M2);
}
__device__ __forceinline__ __half2 u2h2(unsigned u) {
    __half2 h; *reinterpret_cast<unsigned*>(&h) = u; return h;
}
// e5m2 -> half is EXACT byte placement: half bits = fp8 byte << 8.
__device__ __forceinline__ __half2 e5m2_lo(unsigned v) { return u2h2(__byte_perm(v, 0, 0x1404)); }
__device__ __forceinline__ __half2 e5m2_hi(unsigned v) { return u2h2(__byte_perm(v, 0, 0x3424)); }

// ---------------- histograms only ------------------------------------------
__global__ void hist_k(const int* __restrict__ row, const int* __restrict__ col) {
    int t = blockIdx.x * blockDim.x + threadIdx.x;
    if (t < EDGES) {
        atomicAdd(&g_zs.deg[row[t]], 1);
        atomicAdd(&g_zs.colcnt[col[t]], 1);
    }
}

// ---------------- one-kernel scan (shfl-based) + dinv + pad-fill -----------
// Decoupled lookback: block publishes its aggregate BEFORE spinning.
__global__ void __launch_bounds__(1024) scan_k() {
    __shared__ int s_warp[32];
    __shared__ int s_pref;
    int b    = blockIdx.x;
    int tid  = threadIdx.x;
    int lane = tid & 31, wid = tid >> 5;
    int i    = b * SCAN_B + tid;
    int cnt  = (i < N_NODES) ? g_zs.colcnt[i] : 0;
    int v    = (cnt + 3) & ~3;                   // pad to 4
    // warp-level inclusive scan
    int incl = v;
    #pragma unroll
    for (int o = 1; o < 32; o <<= 1) {
        int t = __shfl_up_sync(0xffffffffu, incl, o);
        if (lane >= o) incl += t;
    }
    if (lane == 31) s_warp[wid] = incl;
    __syncthreads();
    if (wid == 0) {                              // scan the 32 warp totals
        int w = s_warp[lane];
        #pragma unroll
        for (int o = 1; o < 32; o <<= 1) {
            int t = __shfl_up_sync(0xffffffffu, w, o);
            if (lane >= o) w += t;
        }
        s_warp[lane] = w;
        if (lane == 31) {                        // publish aggregate first
            atomicExch(&g_aggval[b], w);
            __threadfence();
            atomicExch(&g_zs.flags[b], 1);
        }
    }
    __syncthreads();
    int bincl = incl + (wid ? s_warp[wid - 1] : 0);
    if (i < N_NODES)                             // free rider: dinv
        g_dinv[i] = rsqrtf(fmaxf((float)g_zs.deg[i], 1.0f));
    // lookback: thread t (< b) waits for block t's aggregate
    int pv = 0;
    if (tid < b) {
        while (atomicAdd(&g_zs.flags[tid], 0) == 0) { }
        pv = atomicAdd(&g_aggval[tid], 0);
    }
    #pragma unroll
    for (int o = 16; o; o >>= 1) pv += __shfl_xor_sync(0xffffffffu, pv, o);
    __syncthreads();                             // s_warp reuse barrier
    if (lane == 0) s_warp[wid] = pv;
    __syncthreads();
    if (tid < 32) {
        int w = s_warp[tid];
        #pragma unroll
        for (int o = 16; o; o >>= 1) w += __shfl_xor_sync(0xffffffffu, w, o);
        if (tid == 0) s_pref = w;
    }
    __syncthreads();
    if (i < N_NODES) {
        int off = bincl - v + s_pref;
        g_off[i] = off;
        g_pos[i] = off;
        if (i == N_NODES - 1) g_off[N_NODES] = off + v;
        // fill ONLY the <=3 pad slots with the zero-sentinel row index
        for (int q = off + cnt; q < off + v; q++) g_csr_row[q] = N_NODES;
    }
}

// ---------------- fused: counting-sort scatter + y0 conv (NO barriers) -----
__global__ void scatconv_k(const int* __restrict__ row, const int* __restrict__ col,
                           const float4* __restrict__ embed, uint4* __restrict__ f0) {
    int t = blockIdx.x * blockDim.x + threadIdx.x;
    if (t < EDGES) {
        int p = atomicAdd(&g_pos[col[t]], 1);
        g_csr_row[p] = row[t];
    }
    if (t < N_NODES * 4) {
        int node = t >> 2, lane = t & 3;
        float sc = g_dinv[node] * FSCALE;
        const float4* p = embed + (size_t)node * 16 + lane * 4;
        float4 v0 = p[0], v1 = p[1], v2 = p[2], v3 = p[3];
        uint4 o;
        o.x = (unsigned)f2_f8(v0.x * sc, v0.y * sc) | ((unsigned)f2_f8(v0.z * sc, v0.w * sc) << 16);
        o.y = (unsigned)f2_f8(v1.x * sc, v1.y * sc) | ((unsigned)f2_f8(v1.z * sc, v1.w * sc) << 16);
        o.z = (unsigned)f2_f8(v2.x * sc, v2.y * sc) | ((unsigned)f2_f8(v2.z * sc, v2.w * sc) << 16);
        o.w = (unsigned)f2_f8(v3.x * sc, v3.y * sc) | ((unsigned)f2_f8(v3.z * sc, v3.w * sc) << 16);
        f0[(size_t)node * 4 + lane] = o;
    }
}

// ---------------- one propagation layer: e5m2 gather, pad-4 loop -----------
// 4 lanes/node, 16 dims/lane. Each iter: 1 int4 CSR read = 4 row indices,
// 4x uint4 gathers, 4x acc16. Granularity-4 padding cuts intra-warp
// degree-divergence waste from ~55% to ~31% with no schedule build.
__device__ __forceinline__ void acc16(__half2* a, uint4 v) {
    a[0] = __hadd2(a[0], e5m2_lo(v.x));
    a[1] = __hadd2(a[1], e5m2_hi(v.x));
    a[2] = __hadd2(a[2], e5m2_lo(v.y));
    a[3] = __hadd2(a[3], e5m2_hi(v.y));
    a[4] = __hadd2(a[4], e5m2_lo(v.z));
    a[5] = __hadd2(a[5], e5m2_hi(v.z));
    a[6] = __hadd2(a[6], e5m2_lo(v.w));
    a[7] = __hadd2(a[7], e5m2_hi(v.w));
}

template <bool F8_OUT>
__global__ void __launch_bounds__(256) prop_f8_k(const uint4* __restrict__ yin,
                                                 void* __restrict__ out_v) {
    unsigned t = blockIdx.x * blockDim.x + threadIdx.x;
    unsigned node = t >> 2;
    unsigned lane = t & 3;
    if (node >= N_NODES) return;
    int s = g_off[node];
    int n4 = (g_off[node + 1] - s) >> 2;
    const int4* cp = (const int4*)(g_csr_row + s);   // 16B-aligned (s % 4 == 0)
    __half2 a[8];
    #pragma unroll
    for (int j = 0; j < 8; j++) a[j] = __float2half2_rn(0.f);
    for (int j = 0; j < n4; j++) {
        int4 c = cp[j];
        uint4 v0 = yin[(size_t)c.x * 4 + lane];
        uint4 v1 = yin[(size_t)c.y * 4 + lane];
        uint4 v2 = yin[(size_t)c.z * 4 + lane];
        uint4 v3 = yin[(size_t)c.w * 4 + lane];
        acc16(a, v0); acc16(a, v1); acc16(a, v2); acc16(a, v3);
    }
    float di = g_dinv[node];
    if (F8_OUT) {
        // y_next(scaled) = dinv^2 * sum(scaled)  -- S carries through unchanged
        __half2 sc = __float2half2_rn(di * di);
        uint4 o;
        o.x = (unsigned)h2_f8(__hmul2(a[0], sc)) | ((unsigned)h2_f8(__hmul2(a[1], sc)) << 16);
        o.y = (unsigned)h2_f8(__hmul2(a[2], sc)) | ((unsigned)h2_f8(__hmul2(a[3], sc)) << 16);
        o.z = (unsigned)h2_f8(__hmul2(a[4], sc)) | ((unsigned)h2_f8(__hmul2(a[5], sc)) << 16);
        o.w = (unsigned)h2_f8(__hmul2(a[6], sc)) | ((unsigned)h2_f8(__hmul2(a[7], sc)) << 16);
        ((uint4*)out_v)[(size_t)node * 4 + lane] = o;
    } else {
        // x3 = dinv * sum(scaled) / S   (fp16 for the epilogue; f32 math)
        float sc = di * (1.0f / FSCALE);
        __half2 oh[8];
        #pragma unroll
        for (int j = 0; j < 8; j++) {
            float2 f = __half22float2(a[j]);
            oh[j] = __floats2half2_rn(f.x * sc, f.y * sc);
        }
        uint4* q = (uint4*)out_v + (size_t)node * 8 + lane * 2;  // 16 halves
        uint4 o0, o1;
        o0.x = *reinterpret_cast<unsigned*>(&oh[0]);
        o0.y = *reinterpret_cast<unsigned*>(&oh[1]);
        o0.z = *reinterpret_cast<unsigned*>(&oh[2]);
        o0.w = *reinterpret_cast<unsigned*>(&oh[3]);
        o1.x = *reinterpret_cast<unsigned*>(&oh[4]);
        o1.y = *reinterpret_cast<unsigned*>(&oh[5]);
        o1.z = *reinterpret_cast<unsigned*>(&oh[6]);
        o1.w = *reinterpret_cast<unsigned*>(&oh[7]);
        q[0] = o0; q[1] = o1;
    }
}

// ---------------- fused: batch user counts (uint8) + context sum -----------
__global__ void epi1_k(const int* __restrict__ users, const __half* __restrict__ xh) {
    int b = blockIdx.x, tid = threadIdx.x;
    if (tid < 64) {
        float s = 0.0f;
        #pragma unroll 8
        for (int k = 0; k < 64; k++) {
            int u = users[b * 64 + k];
            s += __half2float(xh[(size_t)u * D + tid]);
        }
        atomicAdd(&g_zs.usum[tid], s);
    } else {
        int u = users[b * 64 + (tid - 64)];
        atomicAdd(&g_zs.cnt8[u >> 2], 1 << ((u & 3) * 8));   // packed uint8
    }
}

// ---------------- softmax-weighted neighbor aggregation over edges ---------
// mx subtraction skipped: cancels exactly in acc/z; clip(1e-12) cannot bind.
__global__ void __launch_bounds__(256) softmax_k(const int* __restrict__ row,
                                                 const int* __restrict__ col,
                                                 const __half* __restrict__ xh) {
    __shared__ float s_us[D];
    __shared__ float s_acc[D];
    __shared__ float s_z;
    int tid = threadIdx.x;
    if (tid < D) {
        s_us[tid]  = g_zs.usum[tid] * (1.0f / (float)BATCH);
        s_acc[tid] = 0.0f;
    }
    if (tid == 0) s_z = 0.0f;
    __syncthreads();

    const unsigned char* cnt8 = (const unsigned char*)g_zs.cnt8;  // 150KB
    int stride = gridDim.x * blockDim.x;
    for (int e = blockIdx.x * blockDim.x + tid; e < EDGES; e += stride) {
        unsigned m = cnt8[row[e]];
        if (m) {                             // ~0.7% of edges
            const uint4* nv = (const uint4*)(xh + (size_t)col[e] * D);  // 8x16B
            float2 vv[32];
            float dot = 0.0f;
            #pragma unroll
            for (int i = 0; i < 8; i++) {
                uint4 q = nv[i];
                vv[4*i+0] = __half22float2(u2h2(q.x));
                vv[4*i+1] = __half22float2(u2h2(q.y));
                vv[4*i+2] = __half22float2(u2h2(q.z));
                vv[4*i+3] = __half22float2(u2h2(q.w));
            }
            #pragma unroll
            for (int i = 0; i < 32; i++)
                dot += vv[i].x * s_us[2*i] + vv[i].y * s_us[2*i+1];
            float w = (float)m * __expf(dot);
            atomicAdd(&s_z, w);
            #pragma unroll
            for (int i = 0; i < 32; i++) {
                atomicAdd(&s_acc[2*i],   w * vv[i].x);
                atomicAdd(&s_acc[2*i+1], w * vv[i].y);
            }
        }
    }
    __syncthreads();
    if (tid < D) atomicAdd(&g_zs.acc[tid], s_acc[tid]);
    if (tid == 0) atomicAdd(&g_zs.z, s_z);
}

// ---------------- final scores: sigmoid(u.i + u.(acc/z)) -------------------
__global__ void score_k(const int* __restrict__ users, const int* __restrict__ items,
                        const __half* __restrict__ xh, float* __restrict__ out) {
    int w = (blockIdx.x * blockDim.x + threadIdx.x) >> 5;
    int lane = threadIdx.x & 31;
    if (w >= BATCH) return;
    int u  = users[w];
    int it = items[w] + NUM_USERS;
    float zc = fmaxf(g_zs.z, 1e-12f);
    float2 ue = __half22float2(((const __half2*)(xh + (size_t)u  * D))[lane]);
    float2 ie = __half22float2(((const __half2*)(xh + (size_t)it * D))[lane]);
    float2 ac = ((const float2*)g_zs.acc)[lane];
    float s = ue.x * ie.x + ue.y * ie.y + (ue.x * ac.x + ue.y * ac.y) / zc;
    #pragma unroll
    for (int o = 16; o; o >>= 1) s += __shfl_xor_sync(0xffffffffu, s, o);
    if (lane == 0) out[w] = 1.0f / (1.0f + __expf(-s));
}

// ---------------- launcher (graph-capturable, allocation-free) -------------
extern "C" void kernel_launch(void* const* d_in, const int* in_sizes, int n_in,
                              void* d_out, int out_size) {
    const float* embed = (const float*)d_in[0];        // [150000, 64] f32
    const int*   row   = (const int*)d_in[1];          // edge_index[0]
    const int*   col   = row + EDGES;                  // edge_index[1]
    const int*   users = (const int*)d_in[2];          // [1024] i32
    const int*   items = (const int*)d_in[3];          // [1024] i32
    float*       out   = (float*)d_out;                // [1024] f32

    void *zsp, *f0p, *f1p, *xhp;
    cudaGetSymbolAddress(&zsp, g_zs);
    cudaGetSymbolAddress(&f0p, g_f0);
    cudaGetSymbolAddress(&f1p, g_f1);
    cudaGetSymbolAddress(&xhp, g_xh);
    const __half* xh = (const __half*)xhp;

    const int EB  = (EDGES + 255) / 256;                // edge-parallel blocks
    const int PB4 = (N_NODES * 4 + 255) / 256;          // 4 threads/node blocks

    cudaMemsetAsync(zsp, 0, sizeof(Zeros));

    hist_k<<<EB, 256>>>(row, col);                      // histograms
    scan_k<<<NBLK, SCAN_B>>>();                         // off/pos + dinv + pad-fill
    scatconv_k<<<EB, 256>>>(row, col, (const float4*)embed, (uint4*)f0p);

    // 3 propagation layers (pad-4, natural order): f0 -> f1 -> f0 -> xh
    prop_f8_k<true ><<<PB4, 256>>>((const uint4*)f0p, f1p);
    prop_f8_k<true ><<<PB4, 256>>>((const uint4*)f1p, f0p);
    prop_f8_k<false><<<PB4, 256>>>((const uint4*)f0p, xhp);

    // batch epilogue (fp16 final layer)
    epi1_k<<<16, 128>>>(users, xh);
    softmax_k<<<1184, 256>>>(row, col, xh);
    score_k<<<BATCH * 32 / 256, 256>>>(users, items, xh, out);
}